// round 8
// baseline (speedup 1.0000x reference)
#include <cuda_runtime.h>
#include <cstdint>

#define S_LEN 512
#define B_SZ  64
#define HIDD  1024
#define EMBD  512
#define NCLS  32000
#define FEATD 2048
#define STEP_SMEM (1024 * 20 * 4)   // hT[1024][20] floats = 80KB

#define FFMA2(d, a, b) asm("fma.rn.f32x2 %0, %1, %2, %0;" : "+l"(d) : "l"(a), "l"(b))
union F2U { unsigned long long u; float2 f; };

// ---- device scratch ----
__device__ float g_G[(size_t)S_LEN * B_SZ * HIDD];     // G + biases (pre-activation seed)
__device__ float g_OUT[(size_t)S_LEN * B_SZ * HIDD];   // h_t
__device__ float g_Wd[(size_t)HIDD * 2 * HIDD];        // W_hh duplicated pairs: [j][2k]=(w,w)
__device__ float g_scores[(S_LEN - 1) * B_SZ];
__device__ float g_attn[(S_LEN - 1) * B_SZ];
__device__ float g_attout[B_SZ * HIDD];

// ---- K0: duplicate W_hh into f32x2-pair layout (once per launch) ----
__global__ void __launch_bounds__(256) wdup_kernel(const float* __restrict__ W_hh) {
    int i = (blockIdx.x * 256 + threadIdx.x) * 4;   // over 1M elements
    if (i < HIDD * HIDD) {
        float4 w = *(const float4*)&W_hh[i];
        int j = i >> 10, k = i & 1023;
        float* dst = &g_Wd[(size_t)j * 2048 + 2 * k];
        *(float2*)&dst[0] = make_float2(w.x, w.x);
        *(float2*)&dst[2] = make_float2(w.y, w.y);
        *(float2*)&dst[4] = make_float2(w.z, w.z);
        *(float2*)&dst[6] = make_float2(w.w, w.w);
    }
}

// ---- K1: gates  G[(t*64+b)][j] = emb[X[b,t]] . W_ih[j] + b_ih[j] + b_hh[j] ----
__global__ void __launch_bounds__(256) gates_kernel(const int* __restrict__ X,
                                                    const float* __restrict__ emb,
                                                    const float* __restrict__ W_ih,
                                                    const float* __restrict__ b_ih,
                                                    const float* __restrict__ b_hh) {
    __shared__ float2 As2[16 * 64];
    __shared__ float  Bs[16 * 68];
    __shared__ int rowidx[64];
    const int n0 = blockIdx.x * 64;
    const int m0 = blockIdx.y * 64;
    const int tid = threadIdx.x;

    if (tid < 64) {
        int m = m0 + tid;
        int t = m >> 6, b = m & 63;
        rowidx[tid] = X[b * S_LEN + t];
    }
    __syncthreads();

    const int tx = tid & 15, ty = tid >> 4;
    unsigned long long acc[4][2];
#pragma unroll
    for (int i = 0; i < 4; i++) { acc[i][0] = 0ull; acc[i][1] = 0ull; }

    const int lm = tid >> 2;
    const int lk = (tid & 3) * 4;

    for (int k0 = 0; k0 < EMBD; k0 += 16) {
        float4 av = *(const float4*)&emb[(size_t)rowidx[lm] * EMBD + k0 + lk];
        As2[(lk + 0) * 64 + lm] = make_float2(av.x, av.x);
        As2[(lk + 1) * 64 + lm] = make_float2(av.y, av.y);
        As2[(lk + 2) * 64 + lm] = make_float2(av.z, av.z);
        As2[(lk + 3) * 64 + lm] = make_float2(av.w, av.w);
        float4 bv = *(const float4*)&W_ih[(size_t)(n0 + lm) * EMBD + k0 + lk];
        Bs[(lk + 0) * 68 + lm] = bv.x; Bs[(lk + 1) * 68 + lm] = bv.y;
        Bs[(lk + 2) * 68 + lm] = bv.z; Bs[(lk + 3) * 68 + lm] = bv.w;
        __syncthreads();
#pragma unroll
        for (int kk = 0; kk < 16; kk++) {
            ulonglong2 a01 = *(const ulonglong2*)&As2[kk * 64 + ty * 4];
            ulonglong2 a23 = *(const ulonglong2*)&As2[kk * 64 + ty * 4 + 2];
            ulonglong2 bp  = *(const ulonglong2*)&Bs[kk * 68 + tx * 4];
            FFMA2(acc[0][0], a01.x, bp.x); FFMA2(acc[0][1], a01.x, bp.y);
            FFMA2(acc[1][0], a01.y, bp.x); FFMA2(acc[1][1], a01.y, bp.y);
            FFMA2(acc[2][0], a23.x, bp.x); FFMA2(acc[2][1], a23.x, bp.y);
            FFMA2(acc[3][0], a23.y, bp.x); FFMA2(acc[3][1], a23.y, bp.y);
        }
        __syncthreads();
    }
    float4 bi = *(const float4*)&b_ih[n0 + tx * 4];
    float4 bh = *(const float4*)&b_hh[n0 + tx * 4];
    float bias[4] = {bi.x + bh.x, bi.y + bh.y, bi.z + bh.z, bi.w + bh.w};
#pragma unroll
    for (int i = 0; i < 4; i++) {
        int m = m0 + ty * 4 + i;
        F2U p0, p1; p0.u = acc[i][0]; p1.u = acc[i][1];
        float4 o = make_float4(p0.f.x + bias[0], p0.f.y + bias[1],
                               p1.f.x + bias[2], p1.f.y + bias[3]);
        *(float4*)&g_G[(size_t)m * HIDD + n0 + tx * 4] = o;
    }
}

// ---- K2: one RNN step. grid (32 jgr, 4 bg) x 128 threads. Full K, no split. ----
// h[t][b][j] = tanh(g_G[t][b][j] + sum_k h[t-1][b][k] * W_hh[j][k])
__global__ void __launch_bounds__(128, 1) step_kernel(int t) {
    extern __shared__ float hT[];   // [1024 k][20] (16 b used)
    const int tid = threadIdx.x;
    const int jgr = blockIdx.x;     // 32 groups of 32 j
    const int bg  = blockIdx.y;     // 4 groups of 16 b

    // ---- stage h(t-1) rows for this CTA's 16 b's, transposed ----
    {
        const int sbb = tid & 15;        // local b
        const int skk = tid >> 4;        // 8 chunks of 128 k
        if (t == 0) {
#pragma unroll
            for (int q = 0; q < 32; q++) {
                int k = skk * 128 + q * 4;
                hT[(k + 0) * 20 + sbb] = 0.f;
                hT[(k + 1) * 20 + sbb] = 0.f;
                hT[(k + 2) * 20 + sbb] = 0.f;
                hT[(k + 3) * 20 + sbb] = 0.f;
            }
        } else {
            const float* hr = g_OUT + (size_t)(t - 1) * B_SZ * HIDD
                            + (size_t)(bg * 16 + sbb) * HIDD + skk * 128;
#pragma unroll
            for (int q = 0; q < 32; q++) {
                float4 hv = __ldcg((const float4*)&hr[q * 4]);
                int k = skk * 128 + q * 4;
                hT[(k + 0) * 20 + sbb] = hv.x;
                hT[(k + 1) * 20 + sbb] = hv.y;
                hT[(k + 2) * 20 + sbb] = hv.z;
                hT[(k + 3) * 20 + sbb] = hv.w;
            }
        }
    }
    __syncthreads();

    // ---- compute: thread = 4 b's x 1 j ----
    const int jj = tid >> 2;             // 0..31
    const int bq = tid & 3;              // 0..3
    const int j = jgr * 32 + jj;
    const int bloc = bq * 4;             // local b base
    const float* wr = &g_Wd[(size_t)j * 2048];

    unsigned long long aL[2] = {0ull, 0ull};   // (b0,b1), k-parity split
    unsigned long long aH[2] = {0ull, 0ull};   // (b2,b3)

#pragma unroll 4
    for (int k = 0; k < HIDD; k += 4) {
        ulonglong2 w01 = *(const ulonglong2*)&wr[2 * k];       // dup(w_k), dup(w_k+1)
        ulonglong2 w23 = *(const ulonglong2*)&wr[2 * k + 4];   // dup(w_k+2), dup(w_k+3)
        ulonglong2 h0 = *(const ulonglong2*)&hT[(k + 0) * 20 + bloc];
        ulonglong2 h1 = *(const ulonglong2*)&hT[(k + 1) * 20 + bloc];
        ulonglong2 h2 = *(const ulonglong2*)&hT[(k + 2) * 20 + bloc];
        ulonglong2 h3 = *(const ulonglong2*)&hT[(k + 3) * 20 + bloc];
        FFMA2(aL[0], h0.x, w01.x); FFMA2(aH[0], h0.y, w01.x);
        FFMA2(aL[1], h1.x, w01.y); FFMA2(aH[1], h1.y, w01.y);
        FFMA2(aL[0], h2.x, w23.x); FFMA2(aH[0], h2.y, w23.x);
        FFMA2(aL[1], h3.x, w23.y); FFMA2(aH[1], h3.y, w23.y);
    }

    F2U l0, l1, hh0, hh1;
    l0.u = aL[0]; l1.u = aL[1]; hh0.u = aH[0]; hh1.u = aH[1];
    float s[4];
    s[0] = l0.f.x + l1.f.x;  s[1] = l0.f.y + l1.f.y;
    s[2] = hh0.f.x + hh1.f.x; s[3] = hh0.f.y + hh1.f.y;

    const size_t base = (size_t)t * B_SZ * HIDD;
#pragma unroll
    for (int i = 0; i < 4; i++) {
        int b = bg * 16 + bq * 4 + i;
        size_t idx = base + (size_t)b * HIDD + j;
        float g = __ldcg(&g_G[idx]);
        g_OUT[idx] = tanhf(g + s[i]);
    }
}

// ---- K3a: scores ----
__global__ void __launch_bounds__(256) scores_kernel() {
    const int s = blockIdx.x;
    const int w = threadIdx.x >> 5, lane = threadIdx.x & 31;
    const float* Pv = g_OUT + (size_t)s * B_SZ * HIDD;
    const float* Lv = g_OUT + (size_t)(S_LEN - 1) * B_SZ * HIDD;
#pragma unroll
    for (int i = 0; i < 8; i++) {
        int b = w * 8 + i;
        const float* p = Pv + (size_t)b * HIDD;
        const float* l = Lv + (size_t)b * HIDD;
        float acc = 0.f;
#pragma unroll 4
        for (int k = lane; k < HIDD; k += 32) acc += p[k] * l[k];
#pragma unroll
        for (int o = 16; o > 0; o >>= 1) acc += __shfl_down_sync(0xffffffffu, acc, o);
        if (lane == 0) g_scores[s * B_SZ + b] = acc;
    }
}

// ---- K3b: softmax over s per b ----
__global__ void __launch_bounds__(512) softmax_kernel() {
    const int b = blockIdx.x;
    const int tid = threadIdx.x;
    __shared__ float red[512];
    float v = (tid < S_LEN - 1) ? g_scores[tid * B_SZ + b] : -1e30f;
    red[tid] = v;
    __syncthreads();
    for (int s = 256; s > 0; s >>= 1) {
        if (tid < s) red[tid] = fmaxf(red[tid], red[tid + s]);
        __syncthreads();
    }
    float m = red[0];
    __syncthreads();
    float e = (tid < S_LEN - 1) ? expf(v - m) : 0.f;
    red[tid] = e;
    __syncthreads();
    for (int s = 256; s > 0; s >>= 1) {
        if (tid < s) red[tid] += red[tid + s];
        __syncthreads();
    }
    float inv = 1.f / red[0];
    if (tid < S_LEN - 1) g_attn[tid * B_SZ + b] = e * inv;
}

// ---- K3c: att_out ----
__global__ void __launch_bounds__(256) attout_kernel() {
    const int b = blockIdx.y;
    const int h = blockIdx.x * 256 + threadIdx.x;
    float acc = 0.f;
#pragma unroll 4
    for (int s = 0; s < S_LEN - 1; s++)
        acc += g_attn[s * B_SZ + b] * g_OUT[(size_t)s * B_SZ * HIDD + (size_t)b * HIDD + h];
    g_attout[b * HIDD + h] = acc;
}

// ---- K4: out GEMM ----
__global__ void __launch_bounds__(256) out_gemm_kernel(const float* __restrict__ W_out,
                                                       const float* __restrict__ b_out,
                                                       float* __restrict__ out) {
    __shared__ float2 Fs2[16 * 64];
    __shared__ float  Ws[16 * 132];
    const int n0 = blockIdx.x * 128;
    const int tid = threadIdx.x;
    const int tx = tid & 31, ty = tid >> 5;
    const float* last = g_OUT + (size_t)(S_LEN - 1) * B_SZ * HIDD;

    unsigned long long acc[8][2];
#pragma unroll
    for (int i = 0; i < 8; i++) { acc[i][0] = 0ull; acc[i][1] = 0ull; }

    const int mm = tid >> 2;
    const int kq = (tid & 3) * 4;

    for (int k0 = 0; k0 < FEATD; k0 += 16) {
        int k = k0 + kq;
        const float* src = (k < HIDD) ? &g_attout[mm * HIDD + k]
                                      : &last[(size_t)mm * HIDD + (k - HIDD)];
        float4 fv = *(const float4*)src;
        Fs2[(kq + 0) * 64 + mm] = make_float2(fv.x, fv.x);
        Fs2[(kq + 1) * 64 + mm] = make_float2(fv.y, fv.y);
        Fs2[(kq + 2) * 64 + mm] = make_float2(fv.z, fv.z);
        Fs2[(kq + 3) * 64 + mm] = make_float2(fv.w, fv.w);
#pragma unroll
        for (int r = 0; r < 2; r++) {
            int f = tid + r * 256;
            int nn = f >> 2;
            int kq2 = (f & 3) * 4;
            float4 wv = *(const float4*)&W_out[(size_t)(n0 + nn) * FEATD + k0 + kq2];
            Ws[(kq2 + 0) * 132 + nn] = wv.x; Ws[(kq2 + 1) * 132 + nn] = wv.y;
            Ws[(kq2 + 2) * 132 + nn] = wv.z; Ws[(kq2 + 3) * 132 + nn] = wv.w;
        }
        __syncthreads();
#pragma unroll
        for (int kk = 0; kk < 16; kk++) {
            ulonglong2 a01 = *(const ulonglong2*)&Fs2[kk * 64 + ty * 8];
            ulonglong2 a23 = *(const ulonglong2*)&Fs2[kk * 64 + ty * 8 + 2];
            ulonglong2 a45 = *(const ulonglong2*)&Fs2[kk * 64 + ty * 8 + 4];
            ulonglong2 a67 = *(const ulonglong2*)&Fs2[kk * 64 + ty * 8 + 6];
            ulonglong2 wp  = *(const ulonglong2*)&Ws[kk * 132 + tx * 4];
            FFMA2(acc[0][0], a01.x, wp.x); FFMA2(acc[0][1], a01.x, wp.y);
            FFMA2(acc[1][0], a01.y, wp.x); FFMA2(acc[1][1], a01.y, wp.y);
            FFMA2(acc[2][0], a23.x, wp.x); FFMA2(acc[2][1], a23.x, wp.y);
            FFMA2(acc[3][0], a23.y, wp.x); FFMA2(acc[3][1], a23.y, wp.y);
            FFMA2(acc[4][0], a45.x, wp.x); FFMA2(acc[4][1], a45.x, wp.y);
            FFMA2(acc[5][0], a45.y, wp.x); FFMA2(acc[5][1], a45.y, wp.y);
            FFMA2(acc[6][0], a67.x, wp.x); FFMA2(acc[6][1], a67.x, wp.y);
            FFMA2(acc[7][0], a67.y, wp.x); FFMA2(acc[7][1], a67.y, wp.y);
        }
        __syncthreads();
    }
    float4 bo = *(const float4*)&b_out[n0 + tx * 4];
#pragma unroll
    for (int i = 0; i < 8; i++) {
        int m = ty * 8 + i;
        F2U p0, p1; p0.u = acc[i][0]; p1.u = acc[i][1];
        float4 o = make_float4(p0.f.x + bo.x, p0.f.y + bo.y,
                               p1.f.x + bo.z, p1.f.y + bo.w);
        *(float4*)&out[(size_t)m * NCLS + n0 + tx * 4] = o;
    }
}

// ---- launch ----
extern "C" void kernel_launch(void* const* d_in, const int* in_sizes, int n_in,
                              void* d_out, int out_size) {
    (void)in_sizes; (void)n_in; (void)out_size;
    const int*   X     = (const int*)d_in[0];
    const float* emb   = (const float*)d_in[1];
    const float* W_ih  = (const float*)d_in[2];
    const float* W_hh  = (const float*)d_in[3];
    const float* b_ih  = (const float*)d_in[4];
    const float* b_hh  = (const float*)d_in[5];
    const float* W_out = (const float*)d_in[6];
    const float* b_out = (const float*)d_in[7];
    float* out = (float*)d_out;

    static bool attr_set = false;
    if (!attr_set) {
        cudaFuncSetAttribute(step_kernel, cudaFuncAttributeMaxDynamicSharedMemorySize, STEP_SMEM);
        attr_set = true;
    }

    wdup_kernel<<<(HIDD * HIDD / 4 + 255) / 256, 256>>>(W_hh);
    gates_kernel<<<dim3(HIDD / 64, (S_LEN * B_SZ) / 64), 256>>>(X, emb, W_ih, b_ih, b_hh);
    for (int t = 0; t < S_LEN; t++)
        step_kernel<<<dim3(32, 4), 128, STEP_SMEM>>>(t);
    scores_kernel<<<S_LEN - 1, 256>>>();
    softmax_kernel<<<B_SZ, 512>>>();
    attout_kernel<<<dim3(HIDD / 256, B_SZ), 256>>>();
    out_gemm_kernel<<<NCLS / 128, 256>>>(W_out, b_out, out);
}

// round 9
// speedup vs baseline: 1.4611x; 1.4611x over previous
#include <cuda_runtime.h>
#include <cstdint>

#define S_LEN 512
#define B_SZ  64
#define HIDD  1024
#define EMBD  512
#define NCLS  32000
#define FEATD 2048
#define RNN_NCTA 128
// Wsh [1024k][32j] = 128KB ; hd dup [512k][32] = 64KB ; red 8KB
#define RNN_SMEM (1024 * 32 * 4 + 512 * 32 * 4 + 4 * 64 * 4 * 8)

#define FFMA2(d, a, b) asm("fma.rn.f32x2 %0, %1, %2, %0;" : "+l"(d) : "l"(a), "l"(b))
union F2U { unsigned long long u; float2 f; };

// ---- device scratch ----
__device__ float g_G[(size_t)S_LEN * B_SZ * HIDD];     // G + biases
__device__ float g_OUT[(size_t)S_LEN * B_SZ * HIDD];   // h_t
__device__ float g_scores[(S_LEN - 1) * B_SZ];
__device__ float g_attn[(S_LEN - 1) * B_SZ];
__device__ float g_attout[B_SZ * HIDD];
__device__ unsigned g_bar_cnt;
__device__ volatile unsigned g_bar_gen;

__global__ void init_kernel() {
    if (blockIdx.x == 0 && threadIdx.x == 0) { g_bar_cnt = 0u; *(unsigned*)&g_bar_gen = 0u; }
}

// ---- K1: gates  G[(t*64+b)][j] = emb[X[b,t]] . W_ih[j] + b_ih[j] + b_hh[j] ----
__global__ void __launch_bounds__(256) gates_kernel(const int* __restrict__ X,
                                                    const float* __restrict__ emb,
                                                    const float* __restrict__ W_ih,
                                                    const float* __restrict__ b_ih,
                                                    const float* __restrict__ b_hh) {
    __shared__ float2 As2[16 * 64];
    __shared__ float  Bs[16 * 68];
    __shared__ int rowidx[64];
    const int n0 = blockIdx.x * 64;
    const int m0 = blockIdx.y * 64;
    const int tid = threadIdx.x;

    if (tid < 64) {
        int m = m0 + tid;
        int t = m >> 6, b = m & 63;
        rowidx[tid] = X[b * S_LEN + t];
    }
    __syncthreads();

    const int tx = tid & 15, ty = tid >> 4;
    unsigned long long acc[4][2];
#pragma unroll
    for (int i = 0; i < 4; i++) { acc[i][0] = 0ull; acc[i][1] = 0ull; }

    const int lm = tid >> 2;
    const int lk = (tid & 3) * 4;

    for (int k0 = 0; k0 < EMBD; k0 += 16) {
        float4 av = *(const float4*)&emb[(size_t)rowidx[lm] * EMBD + k0 + lk];
        As2[(lk + 0) * 64 + lm] = make_float2(av.x, av.x);
        As2[(lk + 1) * 64 + lm] = make_float2(av.y, av.y);
        As2[(lk + 2) * 64 + lm] = make_float2(av.z, av.z);
        As2[(lk + 3) * 64 + lm] = make_float2(av.w, av.w);
        float4 bv = *(const float4*)&W_ih[(size_t)(n0 + lm) * EMBD + k0 + lk];
        Bs[(lk + 0) * 68 + lm] = bv.x; Bs[(lk + 1) * 68 + lm] = bv.y;
        Bs[(lk + 2) * 68 + lm] = bv.z; Bs[(lk + 3) * 68 + lm] = bv.w;
        __syncthreads();
#pragma unroll
        for (int kk = 0; kk < 16; kk++) {
            ulonglong2 a01 = *(const ulonglong2*)&As2[kk * 64 + ty * 4];
            ulonglong2 a23 = *(const ulonglong2*)&As2[kk * 64 + ty * 4 + 2];
            ulonglong2 bp  = *(const ulonglong2*)&Bs[kk * 68 + tx * 4];
            FFMA2(acc[0][0], a01.x, bp.x); FFMA2(acc[0][1], a01.x, bp.y);
            FFMA2(acc[1][0], a01.y, bp.x); FFMA2(acc[1][1], a01.y, bp.y);
            FFMA2(acc[2][0], a23.x, bp.x); FFMA2(acc[2][1], a23.x, bp.y);
            FFMA2(acc[3][0], a23.y, bp.x); FFMA2(acc[3][1], a23.y, bp.y);
        }
        __syncthreads();
    }
    float4 bi = *(const float4*)&b_ih[n0 + tx * 4];
    float4 bh = *(const float4*)&b_hh[n0 + tx * 4];
    float bias[4] = {bi.x + bh.x, bi.y + bh.y, bi.z + bh.z, bi.w + bh.w};
#pragma unroll
    for (int i = 0; i < 4; i++) {
        int m = m0 + ty * 4 + i;
        F2U p0, p1; p0.u = acc[i][0]; p1.u = acc[i][1];
        float4 o = make_float4(p0.f.x + bias[0], p0.f.y + bias[1],
                               p1.f.x + bias[2], p1.f.y + bias[3]);
        *(float4*)&g_G[(size_t)m * HIDD + n0 + tx * 4] = o;
    }
}

// ---- flat grid barrier (R3-proven) ----
__device__ __forceinline__ void grid_bar(unsigned target) {
    __threadfence();
    __syncthreads();
    if (threadIdx.x == 0) {
        unsigned a = atomicAdd(&g_bar_cnt, 1u);
        if (a == (unsigned)(RNN_NCTA - 1)) {
            atomicExch(&g_bar_cnt, 0u);
            __threadfence();
            atomicAdd((unsigned*)&g_bar_gen, 1u);
        } else {
            while (*(volatile unsigned*)&g_bar_gen < target) __nanosleep(32);
        }
        __threadfence();
    }
    __syncthreads();
}

// ---- K2: persistent recurrence — FULL-K per CTA, one barrier/step ----
// grid: CTA c -> jg = c >> 2 (32 j's), bg = c & 3 (16 b's).
// 256 threads = 16 j-tiles(2j) x 4 b-tiles(4b) x 4 k-quarters.
__global__ void __launch_bounds__(256, 1) rnn_kernel(const float* __restrict__ W_hh) {
    extern __shared__ char smem_raw[];
    float* Wsh = (float*)smem_raw;                                   // [1024k][32j]
    float* hd  = (float*)(smem_raw + 1024 * 32 * 4);                 // [512k][2*16b] dup
    unsigned long long* redu = (unsigned long long*)(smem_raw + 1024 * 32 * 4 + 512 * 32 * 4);
    const int tid = threadIdx.x;
    const int c = blockIdx.x;
    const int jg = c >> 2;   // 0..31
    const int bg = c & 3;    // 0..3

    // ---- load W slice: Wsh[k*32 + jl] = W_hh[jg*32+jl][k] ----
    {
        int jl = tid & 31;
        int kc = (tid >> 5) * 128;   // 8 chunks of 128
        const float* wr = &W_hh[(size_t)(jg * 32 + jl) * HIDD + kc];
#pragma unroll
        for (int q = 0; q < 32; q++) {
            float4 wv = *(const float4*)&wr[q * 4];
            Wsh[(kc + q * 4 + 0) * 32 + jl] = wv.x;
            Wsh[(kc + q * 4 + 1) * 32 + jl] = wv.y;
            Wsh[(kc + q * 4 + 2) * 32 + jl] = wv.z;
            Wsh[(kc + q * 4 + 3) * 32 + jl] = wv.w;
        }
    }
    __syncthreads();

    const int q  = tid >> 6;        // k-quarter 0..3
    const int r  = tid & 63;
    const int jt = r & 15;          // j-pair: local j = 2*jt
    const int bt = r >> 4;          // b-tile: local b = 4*bt
    const int sb  = tid & 15;       // staging b
    const int skc = (tid >> 4) * 32; // staging k-chunk within half

    for (int t = 0; t < S_LEN; ++t) {
        unsigned long long acc[4] = {0ull, 0ull, 0ull, 0ull};   // acc[b_i] over j-pair

#pragma unroll
        for (int half = 0; half < 2; half++) {
            // ---- stage h(t-1) half, duplicated: hd[kl*32 + 2b] = (h,h) ----
            if (t == 0) {
#pragma unroll
                for (int qq = 0; qq < 32; qq++) {
                    *(float2*)&hd[(skc + qq) * 32 + 2 * sb] = make_float2(0.f, 0.f);
                }
            } else {
                const float* hr = g_OUT + (size_t)(t - 1) * B_SZ * HIDD
                                + (size_t)(bg * 16 + sb) * HIDD + half * 512 + skc;
#pragma unroll
                for (int qq = 0; qq < 8; qq++) {
                    float4 hv = __ldcg((const float4*)&hr[qq * 4]);
                    int kl = skc + qq * 4;
                    *(float2*)&hd[(kl + 0) * 32 + 2 * sb] = make_float2(hv.x, hv.x);
                    *(float2*)&hd[(kl + 1) * 32 + 2 * sb] = make_float2(hv.y, hv.y);
                    *(float2*)&hd[(kl + 2) * 32 + 2 * sb] = make_float2(hv.z, hv.z);
                    *(float2*)&hd[(kl + 3) * 32 + 2 * sb] = make_float2(hv.w, hv.w);
                }
            }
            __syncthreads();

            // ---- compute this half's k-quarter: kl in [q*128, q*128+128) ----
            const float* wbase = &Wsh[(half * 512) * 32 + 2 * jt];
            const float* hbase = &hd[8 * bt];
#pragma unroll 8
            for (int kl = q * 128; kl < q * 128 + 128; kl++) {
                unsigned long long wp = *(const unsigned long long*)&wbase[kl * 32]; // (wj0,wj1)
                ulonglong2 h01 = *(const ulonglong2*)&hbase[kl * 32];      // dup(b0),dup(b1)
                ulonglong2 h23 = *(const ulonglong2*)&hbase[kl * 32 + 4];  // dup(b2),dup(b3)
                FFMA2(acc[0], h01.x, wp);
                FFMA2(acc[1], h01.y, wp);
                FFMA2(acc[2], h23.x, wp);
                FFMA2(acc[3], h23.y, wp);
            }
            __syncthreads();   // all reads of hd done before next half restages
        }

        // ---- intra-CTA k-quarter reduce ----
#pragma unroll
        for (int i = 0; i < 4; i++) redu[(q * 64 + r) * 4 + i] = acc[i];
        __syncthreads();

        if (tid < 64) {
            const size_t base = (size_t)t * B_SZ * HIDD;
#pragma unroll
            for (int i = 0; i < 4; i++) {
                F2U s0, s1, s2, s3;
                s0.u = redu[(0 * 64 + r) * 4 + i];
                s1.u = redu[(1 * 64 + r) * 4 + i];
                s2.u = redu[(2 * 64 + r) * 4 + i];
                s3.u = redu[(3 * 64 + r) * 4 + i];
                float sx = s0.f.x + s1.f.x + s2.f.x + s3.f.x;
                float sy = s0.f.y + s1.f.y + s2.f.y + s3.f.y;
                int b = bg * 16 + 4 * bt + i;
                size_t idx = base + (size_t)b * HIDD + jg * 32 + 2 * jt;
                float2 g = __ldcg((const float2*)&g_G[idx]);
                float2 o = make_float2(tanhf(g.x + sx), tanhf(g.y + sy));
                __stcg((float2*)&g_OUT[idx], o);
            }
        }
        grid_bar((unsigned)(t + 1));
    }
}

// ---- K3a: scores ----
__global__ void __launch_bounds__(256) scores_kernel() {
    const int s = blockIdx.x;
    const int w = threadIdx.x >> 5, lane = threadIdx.x & 31;
    const float* Pv = g_OUT + (size_t)s * B_SZ * HIDD;
    const float* Lv = g_OUT + (size_t)(S_LEN - 1) * B_SZ * HIDD;
#pragma unroll
    for (int i = 0; i < 8; i++) {
        int b = w * 8 + i;
        const float* p = Pv + (size_t)b * HIDD;
        const float* l = Lv + (size_t)b * HIDD;
        float acc = 0.f;
#pragma unroll 4
        for (int k = lane; k < HIDD; k += 32) acc += p[k] * l[k];
#pragma unroll
        for (int o = 16; o > 0; o >>= 1) acc += __shfl_down_sync(0xffffffffu, acc, o);
        if (lane == 0) g_scores[s * B_SZ + b] = acc;
    }
}

// ---- K3b: softmax over s per b ----
__global__ void __launch_bounds__(512) softmax_kernel() {
    const int b = blockIdx.x;
    const int tid = threadIdx.x;
    __shared__ float red[512];
    float v = (tid < S_LEN - 1) ? g_scores[tid * B_SZ + b] : -1e30f;
    red[tid] = v;
    __syncthreads();
    for (int s = 256; s > 0; s >>= 1) {
        if (tid < s) red[tid] = fmaxf(red[tid], red[tid + s]);
        __syncthreads();
    }
    float m = red[0];
    __syncthreads();
    float e = (tid < S_LEN - 1) ? expf(v - m) : 0.f;
    red[tid] = e;
    __syncthreads();
    for (int s = 256; s > 0; s >>= 1) {
        if (tid < s) red[tid] += red[tid + s];
        __syncthreads();
    }
    float inv = 1.f / red[0];
    if (tid < S_LEN - 1) g_attn[tid * B_SZ + b] = e * inv;
}

// ---- K3c: att_out ----
__global__ void __launch_bounds__(256) attout_kernel() {
    const int b = blockIdx.y;
    const int h = blockIdx.x * 256 + threadIdx.x;
    float acc = 0.f;
#pragma unroll 4
    for (int s = 0; s < S_LEN - 1; s++)
        acc += g_attn[s * B_SZ + b] * g_OUT[(size_t)s * B_SZ * HIDD + (size_t)b * HIDD + h];
    g_attout[b * HIDD + h] = acc;
}

// ---- K4: out GEMM ----
__global__ void __launch_bounds__(256) out_gemm_kernel(const float* __restrict__ W_out,
                                                       const float* __restrict__ b_out,
                                                       float* __restrict__ out) {
    __shared__ float2 Fs2[16 * 64];
    __shared__ float  Ws[16 * 132];
    const int n0 = blockIdx.x * 128;
    const int tid = threadIdx.x;
    const int tx = tid & 31, ty = tid >> 5;
    const float* last = g_OUT + (size_t)(S_LEN - 1) * B_SZ * HIDD;

    unsigned long long acc[8][2];
#pragma unroll
    for (int i = 0; i < 8; i++) { acc[i][0] = 0ull; acc[i][1] = 0ull; }

    const int mm = tid >> 2;
    const int kq = (tid & 3) * 4;

    for (int k0 = 0; k0 < FEATD; k0 += 16) {
        int k = k0 + kq;
        const float* src = (k < HIDD) ? &g_attout[mm * HIDD + k]
                                      : &last[(size_t)mm * HIDD + (k - HIDD)];
        float4 fv = *(const float4*)src;
        Fs2[(kq + 0) * 64 + mm] = make_float2(fv.x, fv.x);
        Fs2[(kq + 1) * 64 + mm] = make_float2(fv.y, fv.y);
        Fs2[(kq + 2) * 64 + mm] = make_float2(fv.z, fv.z);
        Fs2[(kq + 3) * 64 + mm] = make_float2(fv.w, fv.w);
#pragma unroll
        for (int rr = 0; rr < 2; rr++) {
            int f = tid + rr * 256;
            int nn = f >> 2;
            int kq2 = (f & 3) * 4;
            float4 wv = *(const float4*)&W_out[(size_t)(n0 + nn) * FEATD + k0 + kq2];
            Ws[(kq2 + 0) * 132 + nn] = wv.x; Ws[(kq2 + 1) * 132 + nn] = wv.y;
            Ws[(kq2 + 2) * 132 + nn] = wv.z; Ws[(kq2 + 3) * 132 + nn] = wv.w;
        }
        __syncthreads();
#pragma unroll
        for (int kk = 0; kk < 16; kk++) {
            ulonglong2 a01 = *(const ulonglong2*)&Fs2[kk * 64 + ty * 8];
            ulonglong2 a23 = *(const ulonglong2*)&Fs2[kk * 64 + ty * 8 + 2];
            ulonglong2 a45 = *(const ulonglong2*)&Fs2[kk * 64 + ty * 8 + 4];
            ulonglong2 a67 = *(const ulonglong2*)&Fs2[kk * 64 + ty * 8 + 6];
            ulonglong2 wp  = *(const ulonglong2*)&Ws[kk * 132 + tx * 4];
            FFMA2(acc[0][0], a01.x, wp.x); FFMA2(acc[0][1], a01.x, wp.y);
            FFMA2(acc[1][0], a01.y, wp.x); FFMA2(acc[1][1], a01.y, wp.y);
            FFMA2(acc[2][0], a23.x, wp.x); FFMA2(acc[2][1], a23.x, wp.y);
            FFMA2(acc[3][0], a23.y, wp.x); FFMA2(acc[3][1], a23.y, wp.y);
            FFMA2(acc[4][0], a45.x, wp.x); FFMA2(acc[4][1], a45.x, wp.y);
            FFMA2(acc[5][0], a45.y, wp.x); FFMA2(acc[5][1], a45.y, wp.y);
            FFMA2(acc[6][0], a67.x, wp.x); FFMA2(acc[6][1], a67.x, wp.y);
            FFMA2(acc[7][0], a67.y, wp.x); FFMA2(acc[7][1], a67.y, wp.y);
        }
        __syncthreads();
    }
    float4 bo = *(const float4*)&b_out[n0 + tx * 4];
#pragma unroll
    for (int i = 0; i < 8; i++) {
        int m = ty * 8 + i;
        F2U p0, p1; p0.u = acc[i][0]; p1.u = acc[i][1];
        float4 o = make_float4(p0.f.x + bo.x, p0.f.y + bo.y,
                               p1.f.x + bo.z, p1.f.y + bo.w);
        *(float4*)&out[(size_t)m * NCLS + n0 + tx * 4] = o;
    }
}

// ---- launch ----
extern "C" void kernel_launch(void* const* d_in, const int* in_sizes, int n_in,
                              void* d_out, int out_size) {
    (void)in_sizes; (void)n_in; (void)out_size;
    const int*   X     = (const int*)d_in[0];
    const float* emb   = (const float*)d_in[1];
    const float* W_ih  = (const float*)d_in[2];
    const float* W_hh  = (const float*)d_in[3];
    const float* b_ih  = (const float*)d_in[4];
    const float* b_hh  = (const float*)d_in[5];
    const float* W_out = (const float*)d_in[6];
    const float* b_out = (const float*)d_in[7];
    float* out = (float*)d_out;

    static bool attr_set = false;
    if (!attr_set) {
        cudaFuncSetAttribute(rnn_kernel, cudaFuncAttributeMaxDynamicSharedMemorySize, RNN_SMEM);
        attr_set = true;
    }

    init_kernel<<<1, 32>>>();
    gates_kernel<<<dim3(HIDD / 64, (S_LEN * B_SZ) / 64), 256>>>(X, emb, W_ih, b_ih, b_hh);
    rnn_kernel<<<RNN_NCTA, 256, RNN_SMEM>>>(W_hh);
    scores_kernel<<<S_LEN - 1, 256>>>();
    softmax_kernel<<<B_SZ, 512>>>();
    attout_kernel<<<dim3(HIDD / 256, B_SZ), 256>>>();
    out_gemm_kernel<<<NCLS / 128, 256>>>(W_out, b_out, out);
}

// round 10
// speedup vs baseline: 1.6375x; 1.1208x over previous
#include <cuda_runtime.h>
#include <cstdint>

#define S_LEN 512
#define B_SZ  64
#define HIDD  1024
#define EMBD  512
#define NCLS  32000
#define FEATD 2048
#define RNN_NCTA 128
#define RNN_KS 8
// hshf [128k][64b] float = 32KB ; Wd dup [128k][128] float = 64KB
#define RNN_SMEM (128 * 64 * 4 + 128 * 128 * 4)

#define FFMA2(d, a, b) asm("fma.rn.f32x2 %0, %1, %2, %0;" : "+l"(d) : "l"(a), "l"(b))
union F2U { unsigned long long u; float2 f; };

// ---- device scratch ----
__device__ float g_G[(size_t)S_LEN * B_SZ * HIDD];
__device__ float g_OUT[(size_t)S_LEN * B_SZ * HIDD];
__device__ float g_P[RNN_KS * B_SZ * HIDD];
__device__ float g_h0[B_SZ * HIDD];
__device__ float g_scores[(S_LEN - 1) * B_SZ];
__device__ float g_attn[(S_LEN - 1) * B_SZ];
__device__ float g_attout[B_SZ * HIDD];
__device__ unsigned g_bar_grp[8 * 32];   // 8 counters on distinct 128B lines
__device__ unsigned g_bar_root;
__device__ volatile unsigned g_bar_gen;

__global__ void init_kernel() {
    int i = blockIdx.x * blockDim.x + threadIdx.x;
    if (i < B_SZ * HIDD) g_h0[i] = 0.f;
    if (i < 8 * 32) g_bar_grp[i] = 0u;
    if (i == 0) { g_bar_root = 0u; *(unsigned*)&g_bar_gen = 0u; }
}

// ---- K1: gates  G[(t*64+b)][j] = emb[X[b,t]] . W_ih[j] + b_ih[j] + b_hh[j] ----
__global__ void __launch_bounds__(256) gates_kernel(const int* __restrict__ X,
                                                    const float* __restrict__ emb,
                                                    const float* __restrict__ W_ih,
                                                    const float* __restrict__ b_ih,
                                                    const float* __restrict__ b_hh) {
    __shared__ float2 As2[16 * 64];
    __shared__ float  Bs[16 * 68];
    __shared__ int rowidx[64];
    const int n0 = blockIdx.x * 64;
    const int m0 = blockIdx.y * 64;
    const int tid = threadIdx.x;

    if (tid < 64) {
        int m = m0 + tid;
        int t = m >> 6, b = m & 63;
        rowidx[tid] = X[b * S_LEN + t];
    }
    __syncthreads();

    const int tx = tid & 15, ty = tid >> 4;
    unsigned long long acc[4][2];
#pragma unroll
    for (int i = 0; i < 4; i++) { acc[i][0] = 0ull; acc[i][1] = 0ull; }

    const int lm = tid >> 2;
    const int lk = (tid & 3) * 4;

    for (int k0 = 0; k0 < EMBD; k0 += 16) {
        float4 av = *(const float4*)&emb[(size_t)rowidx[lm] * EMBD + k0 + lk];
        As2[(lk + 0) * 64 + lm] = make_float2(av.x, av.x);
        As2[(lk + 1) * 64 + lm] = make_float2(av.y, av.y);
        As2[(lk + 2) * 64 + lm] = make_float2(av.z, av.z);
        As2[(lk + 3) * 64 + lm] = make_float2(av.w, av.w);
        float4 bv = *(const float4*)&W_ih[(size_t)(n0 + lm) * EMBD + k0 + lk];
        Bs[(lk + 0) * 68 + lm] = bv.x; Bs[(lk + 1) * 68 + lm] = bv.y;
        Bs[(lk + 2) * 68 + lm] = bv.z; Bs[(lk + 3) * 68 + lm] = bv.w;
        __syncthreads();
#pragma unroll
        for (int kk = 0; kk < 16; kk++) {
            ulonglong2 a01 = *(const ulonglong2*)&As2[kk * 64 + ty * 4];
            ulonglong2 a23 = *(const ulonglong2*)&As2[kk * 64 + ty * 4 + 2];
            ulonglong2 bp  = *(const ulonglong2*)&Bs[kk * 68 + tx * 4];
            FFMA2(acc[0][0], a01.x, bp.x); FFMA2(acc[0][1], a01.x, bp.y);
            FFMA2(acc[1][0], a01.y, bp.x); FFMA2(acc[1][1], a01.y, bp.y);
            FFMA2(acc[2][0], a23.x, bp.x); FFMA2(acc[2][1], a23.x, bp.y);
            FFMA2(acc[3][0], a23.y, bp.x); FFMA2(acc[3][1], a23.y, bp.y);
        }
        __syncthreads();
    }
    float4 bi = *(const float4*)&b_ih[n0 + tx * 4];
    float4 bh = *(const float4*)&b_hh[n0 + tx * 4];
    float bias[4] = {bi.x + bh.x, bi.y + bh.y, bi.z + bh.z, bi.w + bh.w};
#pragma unroll
    for (int i = 0; i < 4; i++) {
        int m = m0 + ty * 4 + i;
        F2U p0, p1; p0.u = acc[i][0]; p1.u = acc[i][1];
        float4 o = make_float4(p0.f.x + bias[0], p0.f.y + bias[1],
                               p1.f.x + bias[2], p1.f.y + bias[3]);
        *(float4*)&g_G[(size_t)m * HIDD + n0 + tx * 4] = o;
    }
}

// ---- tree grid barrier: 8 parallel arrive lines (16 CTAs each) + root ----
__device__ __forceinline__ void grid_bar(unsigned target, int cta) {
    __threadfence();
    __syncthreads();
    if (threadIdx.x == 0) {
        unsigned grp = (unsigned)(cta & 7);
        unsigned a = atomicAdd(&g_bar_grp[grp * 32], 1u);
        if (a == 15u) {
            unsigned r = atomicAdd(&g_bar_root, 1u);
            if (r == 7u) {
                g_bar_root = 0u;
#pragma unroll
                for (int g = 0; g < 8; g++) g_bar_grp[g * 32] = 0u;
                __threadfence();
                atomicAdd((unsigned*)&g_bar_gen, 1u);
            }
        }
        while (*(volatile unsigned*)&g_bar_gen < target) __nanosleep(16);
        __threadfence();
    }
    __syncthreads();
}

// ---- K2: persistent recurrence, K-split 8, tile 8b x 4j, W pre-dup in SMEM ----
// CTA c: jg = c & 15 (64 j-cols), ks = c >> 4 (128 k each).
__global__ void __launch_bounds__(128, 1) rnn_kernel(const float* __restrict__ W_hh) {
    extern __shared__ char smem_raw[];
    float* hshf = (float*)smem_raw;                    // [128k][64b] undup
    float* Wd   = (float*)(smem_raw + 128 * 64 * 4);   // [128k][128] dup: Wd[k][2j]=(w,w)
    const int tid = threadIdx.x;
    const int c = blockIdx.x;
    const int jg = c & 15;   // 64 j-cols per group
    const int ks = c >> 4;   // 128 K each

    // resident W slice, k-major, duplicated
    {
        int jl = tid & 63;
        int kc = (tid >> 6) * 64;
        const float* wr = &W_hh[(size_t)(jg * 64 + jl) * HIDD + ks * 128 + kc];
#pragma unroll
        for (int q = 0; q < 16; q++) {
            float4 wv = *(const float4*)&wr[q * 4];
            *(float2*)&Wd[(kc + q * 4 + 0) * 128 + 2 * jl] = make_float2(wv.x, wv.x);
            *(float2*)&Wd[(kc + q * 4 + 1) * 128 + 2 * jl] = make_float2(wv.y, wv.y);
            *(float2*)&Wd[(kc + q * 4 + 2) * 128 + 2 * jl] = make_float2(wv.z, wv.z);
            *(float2*)&Wd[(kc + q * 4 + 3) * 128 + 2 * jl] = make_float2(wv.w, wv.w);
        }
    }
    __syncthreads();

    const int b0  = (tid & 7) * 8;    // 8 b's per thread
    const int jl0 = (tid >> 3) * 4;   // 4 j's per thread (local)
    const int sb  = tid & 63;         // staging batch
    const int skc = (tid >> 6) * 64;  // staging k-chunk
    unsigned tgt = 0;

    for (int t = 0; t < S_LEN; ++t) {
        const float* hprev = (t == 0) ? g_h0 : (g_OUT + (size_t)(t - 1) * B_SZ * HIDD);
        // stage h transposed, undup: hshf[k*64+b] = h[b][k]
        {
            const float* hr = &hprev[(size_t)sb * HIDD + ks * 128 + skc];
#pragma unroll
            for (int q = 0; q < 16; q++) {
                float4 hv = __ldcg((const float4*)&hr[q * 4]);
                hshf[(skc + q * 4 + 0) * 64 + sb] = hv.x;
                hshf[(skc + q * 4 + 1) * 64 + sb] = hv.y;
                hshf[(skc + q * 4 + 2) * 64 + sb] = hv.z;
                hshf[(skc + q * 4 + 3) * 64 + sb] = hv.w;
            }
        }
        __syncthreads();

        unsigned long long acc[4][4];   // acc[j][bp]
#pragma unroll
        for (int i = 0; i < 4; i++)
#pragma unroll
            for (int p = 0; p < 4; p++) acc[i][p] = 0ull;

#pragma unroll 8
        for (int kk = 0; kk < 128; kk++) {
            ulonglong2 hA = *(const ulonglong2*)&hshf[kk * 64 + b0];      // (b0,b1),(b2,b3)
            ulonglong2 hB = *(const ulonglong2*)&hshf[kk * 64 + b0 + 4];  // (b4,b5),(b6,b7)
            ulonglong2 w01 = *(const ulonglong2*)&Wd[kk * 128 + 2 * jl0];     // dup(j0), dup(j1)
            ulonglong2 w23 = *(const ulonglong2*)&Wd[kk * 128 + 2 * jl0 + 4]; // dup(j2), dup(j3)
            FFMA2(acc[0][0], hA.x, w01.x); FFMA2(acc[0][1], hA.y, w01.x);
            FFMA2(acc[0][2], hB.x, w01.x); FFMA2(acc[0][3], hB.y, w01.x);
            FFMA2(acc[1][0], hA.x, w01.y); FFMA2(acc[1][1], hA.y, w01.y);
            FFMA2(acc[1][2], hB.x, w01.y); FFMA2(acc[1][3], hB.y, w01.y);
            FFMA2(acc[2][0], hA.x, w23.x); FFMA2(acc[2][1], hA.y, w23.x);
            FFMA2(acc[2][2], hB.x, w23.x); FFMA2(acc[2][3], hB.y, w23.x);
            FFMA2(acc[3][0], hA.x, w23.y); FFMA2(acc[3][1], hA.y, w23.y);
            FFMA2(acc[3][2], hB.x, w23.y); FFMA2(acc[3][3], hB.y, w23.y);
        }

        // write partials: g_P[ks][b][jg*64 + jl0 .. +3]
#pragma unroll
        for (int p = 0; p < 4; p++) {
            F2U a0, a1, a2, a3;
            a0.u = acc[0][p]; a1.u = acc[1][p]; a2.u = acc[2][p]; a3.u = acc[3][p];
            float4 lo = make_float4(a0.f.x, a1.f.x, a2.f.x, a3.f.x);
            float4 hi = make_float4(a0.f.y, a1.f.y, a2.f.y, a3.f.y);
            *(float4*)&g_P[ks * (B_SZ * HIDD) + (b0 + 2 * p) * HIDD + jg * 64 + jl0] = lo;
            *(float4*)&g_P[ks * (B_SZ * HIDD) + (b0 + 2 * p + 1) * HIDD + jg * 64 + jl0] = hi;
        }
        grid_bar(++tgt, c);

        // combine: 512 contiguous elements per CTA, sum 8 partials
        {
            int base = c * 512 + tid * 4;
            float4 s = __ldcg((const float4*)&g_P[base]);
#pragma unroll
            for (int sp = 1; sp < RNN_KS; sp++) {
                float4 p = __ldcg((const float4*)&g_P[sp * (B_SZ * HIDD) + base]);
                s.x += p.x; s.y += p.y; s.z += p.z; s.w += p.w;
            }
            float4 g = __ldcg((const float4*)&g_G[(size_t)t * B_SZ * HIDD + base]);
            float4 o;
            o.x = tanhf(g.x + s.x);
            o.y = tanhf(g.y + s.y);
            o.z = tanhf(g.z + s.z);
            o.w = tanhf(g.w + s.w);
            *(float4*)&g_OUT[(size_t)t * B_SZ * HIDD + base] = o;
        }
        grid_bar(++tgt, c);
    }
}

// ---- K3a: scores ----
__global__ void __launch_bounds__(256) scores_kernel() {
    const int s = blockIdx.x;
    const int w = threadIdx.x >> 5, lane = threadIdx.x & 31;
    const float* Pv = g_OUT + (size_t)s * B_SZ * HIDD;
    const float* Lv = g_OUT + (size_t)(S_LEN - 1) * B_SZ * HIDD;
#pragma unroll
    for (int i = 0; i < 8; i++) {
        int b = w * 8 + i;
        const float* p = Pv + (size_t)b * HIDD;
        const float* l = Lv + (size_t)b * HIDD;
        float acc = 0.f;
#pragma unroll 4
        for (int k = lane; k < HIDD; k += 32) acc += p[k] * l[k];
#pragma unroll
        for (int o = 16; o > 0; o >>= 1) acc += __shfl_down_sync(0xffffffffu, acc, o);
        if (lane == 0) g_scores[s * B_SZ + b] = acc;
    }
}

// ---- K3b: softmax over s per b ----
__global__ void __launch_bounds__(512) softmax_kernel() {
    const int b = blockIdx.x;
    const int tid = threadIdx.x;
    __shared__ float red[512];
    float v = (tid < S_LEN - 1) ? g_scores[tid * B_SZ + b] : -1e30f;
    red[tid] = v;
    __syncthreads();
    for (int s = 256; s > 0; s >>= 1) {
        if (tid < s) red[tid] = fmaxf(red[tid], red[tid + s]);
        __syncthreads();
    }
    float m = red[0];
    __syncthreads();
    float e = (tid < S_LEN - 1) ? expf(v - m) : 0.f;
    red[tid] = e;
    __syncthreads();
    for (int s = 256; s > 0; s >>= 1) {
        if (tid < s) red[tid] += red[tid + s];
        __syncthreads();
    }
    float inv = 1.f / red[0];
    if (tid < S_LEN - 1) g_attn[tid * B_SZ + b] = e * inv;
}

// ---- K3c: att_out ----
__global__ void __launch_bounds__(256) attout_kernel() {
    const int b = blockIdx.y;
    const int h = blockIdx.x * 256 + threadIdx.x;
    float acc = 0.f;
#pragma unroll 4
    for (int s = 0; s < S_LEN - 1; s++)
        acc += g_attn[s * B_SZ + b] * g_OUT[(size_t)s * B_SZ * HIDD + (size_t)b * HIDD + h];
    g_attout[b * HIDD + h] = acc;
}

// ---- K4: out GEMM ----
__global__ void __launch_bounds__(256) out_gemm_kernel(const float* __restrict__ W_out,
                                                       const float* __restrict__ b_out,
                                                       float* __restrict__ out) {
    __shared__ float2 Fs2[16 * 64];
    __shared__ float  Ws[16 * 132];
    const int n0 = blockIdx.x * 128;
    const int tid = threadIdx.x;
    const int tx = tid & 31, ty = tid >> 5;
    const float* last = g_OUT + (size_t)(S_LEN - 1) * B_SZ * HIDD;

    unsigned long long acc[8][2];
#pragma unroll
    for (int i = 0; i < 8; i++) { acc[i][0] = 0ull; acc[i][1] = 0ull; }

    const int mm = tid >> 2;
    const int kq = (tid & 3) * 4;

    for (int k0 = 0; k0 < FEATD; k0 += 16) {
        int k = k0 + kq;
        const float* src = (k < HIDD) ? &g_attout[mm * HIDD + k]
                                      : &last[(size_t)mm * HIDD + (k - HIDD)];
        float4 fv = *(const float4*)src;
        Fs2[(kq + 0) * 64 + mm] = make_float2(fv.x, fv.x);
        Fs2[(kq + 1) * 64 + mm] = make_float2(fv.y, fv.y);
        Fs2[(kq + 2) * 64 + mm] = make_float2(fv.z, fv.z);
        Fs2[(kq + 3) * 64 + mm] = make_float2(fv.w, fv.w);
#pragma unroll
        for (int r = 0; r < 2; r++) {
            int f = tid + r * 256;
            int nn = f >> 2;
            int kq2 = (f & 3) * 4;
            float4 wv = *(const float4*)&W_out[(size_t)(n0 + nn) * FEATD + k0 + kq2];
            Ws[(kq2 + 0) * 132 + nn] = wv.x; Ws[(kq2 + 1) * 132 + nn] = wv.y;
            Ws[(kq2 + 2) * 132 + nn] = wv.z; Ws[(kq2 + 3) * 132 + nn] = wv.w;
        }
        __syncthreads();
#pragma unroll
        for (int kk = 0; kk < 16; kk++) {
            ulonglong2 a01 = *(const ulonglong2*)&Fs2[kk * 64 + ty * 8];
            ulonglong2 a23 = *(const ulonglong2*)&Fs2[kk * 64 + ty * 8 + 2];
            ulonglong2 a45 = *(const ulonglong2*)&Fs2[kk * 64 + ty * 8 + 4];
            ulonglong2 a67 = *(const ulonglong2*)&Fs2[kk * 64 + ty * 8 + 6];
            ulonglong2 wp  = *(const ulonglong2*)&Ws[kk * 132 + tx * 4];
            FFMA2(acc[0][0], a01.x, wp.x); FFMA2(acc[0][1], a01.x, wp.y);
            FFMA2(acc[1][0], a01.y, wp.x); FFMA2(acc[1][1], a01.y, wp.y);
            FFMA2(acc[2][0], a23.x, wp.x); FFMA2(acc[2][1], a23.x, wp.y);
            FFMA2(acc[3][0], a23.y, wp.x); FFMA2(acc[3][1], a23.y, wp.y);
            FFMA2(acc[4][0], a45.x, wp.x); FFMA2(acc[4][1], a45.x, wp.y);
            FFMA2(acc[5][0], a45.y, wp.x); FFMA2(acc[5][1], a45.y, wp.y);
            FFMA2(acc[6][0], a67.x, wp.x); FFMA2(acc[6][1], a67.x, wp.y);
            FFMA2(acc[7][0], a67.y, wp.x); FFMA2(acc[7][1], a67.y, wp.y);
        }
        __syncthreads();
    }
    float4 bo = *(const float4*)&b_out[n0 + tx * 4];
#pragma unroll
    for (int i = 0; i < 8; i++) {
        int m = ty * 8 + i;
        F2U p0, p1; p0.u = acc[i][0]; p1.u = acc[i][1];
        float4 o = make_float4(p0.f.x + bo.x, p0.f.y + bo.y,
                               p1.f.x + bo.z, p1.f.y + bo.w);
        *(float4*)&out[(size_t)m * NCLS + n0 + tx * 4] = o;
    }
}

// ---- launch ----
extern "C" void kernel_launch(void* const* d_in, const int* in_sizes, int n_in,
                              void* d_out, int out_size) {
    (void)in_sizes; (void)n_in; (void)out_size;
    const int*   X     = (const int*)d_in[0];
    const float* emb   = (const float*)d_in[1];
    const float* W_ih  = (const float*)d_in[2];
    const float* W_hh  = (const float*)d_in[3];
    const float* b_ih  = (const float*)d_in[4];
    const float* b_hh  = (const float*)d_in[5];
    const float* W_out = (const float*)d_in[6];
    const float* b_out = (const float*)d_in[7];
    float* out = (float*)d_out;

    static bool attr_set = false;
    if (!attr_set) {
        cudaFuncSetAttribute(rnn_kernel, cudaFuncAttributeMaxDynamicSharedMemorySize, RNN_SMEM);
        attr_set = true;
    }

    init_kernel<<<256, 256>>>();
    gates_kernel<<<dim3(HIDD / 64, (S_LEN * B_SZ) / 64), 256>>>(X, emb, W_ih, b_ih, b_hh);
    rnn_kernel<<<RNN_NCTA, 128, RNN_SMEM>>>(W_hh);
    scores_kernel<<<S_LEN - 1, 256>>>();
    softmax_kernel<<<B_SZ, 512>>>();
    attout_kernel<<<dim3(HIDD / 256, B_SZ), 256>>>();
    out_gemm_kernel<<<NCLS / 128, 256>>>(W_out, b_out, out);
}